// round 11
// baseline (speedup 1.0000x reference)
#include <cuda_runtime.h>
#include <cstdint>

#define NTHREADS 256
#define KTOP 30
#define CCOLS 32000
#define NF4 8000          // float4 per row
#define BOOT4 2048        // float4 in bootstrap chunk (8192 floats)
#define CAP 1024
#define MAXB 4096

__device__ float g_rowloss[MAXB];
__device__ unsigned g_done = 0;

__device__ __forceinline__ unsigned ordu(float f) {
    unsigned u = __float_as_uint(f);
    return (u & 0x80000000u) ? ~u : (u | 0x80000000u);
}
// key: order-preserving float in high bits, ~index low => unique keys,
// equal values break ties toward smaller index (matches jax top_k).
__device__ __forceinline__ unsigned long long mkkey(float f, unsigned idx) {
    return (((unsigned long long)ordu(f)) << 32) | (unsigned long long)(~idx);
}

struct SMem {
    unsigned long long buf[CAP];
    unsigned long long wred[8];
    float gmax[64];
    int   tIdx[KTOP];
    int   lIdx[KTOP];
    float th;
    int   cnt;
    int   isLast;
};

// Push candidates from one float4 iff its max beats th (rare path).
__device__ __forceinline__ void filt4(const float4& v, unsigned e, float th, SMem* s) {
    float vm = fmaxf(fmaxf(v.x, v.y), fmaxf(v.z, v.w));
    if (vm >= th) {   // ~1.5% of float4s
        if (v.x >= th) { int p = atomicAdd(&s->cnt, 1); if (p < CAP) s->buf[p] = mkkey(v.x, e); }
        if (v.y >= th) { int p = atomicAdd(&s->cnt, 1); if (p < CAP) s->buf[p] = mkkey(v.y, e + 1); }
        if (v.z >= th) { int p = atomicAdd(&s->cnt, 1); if (p < CAP) s->buf[p] = mkkey(v.z, e + 2); }
        if (v.w >= th) { int p = atomicAdd(&s->cnt, 1); if (p < CAP) s->buf[p] = mkkey(v.w, e + 3); }
    }
}

// Exact top-30 index set of one row. On return (synced): outIdx[0..29] filled
// (rank order, but callers only treat it as a set).
__device__ void topk_select(const float4* __restrict__ row4, SMem* s, int* outIdx) {
    const int tid = threadIdx.x;
    if (tid == 0) s->cnt = 0;

    // ---- Bootstrap: load first 8192 elems into regs, derive safe threshold ----
    float4 w[8];
    float m = -3.402823466e38f;
#pragma unroll
    for (int k = 0; k < 8; k++) {
        w[k] = __ldg(&row4[tid + (k << 8)]);
        m = fmaxf(m, fmaxf(fmaxf(w[k].x, w[k].y), fmaxf(w[k].z, w[k].w)));
    }
    m = fmaxf(m, __shfl_xor_sync(0xFFFFFFFFu, m, 1));
    m = fmaxf(m, __shfl_xor_sync(0xFFFFFFFFu, m, 2));
    if ((tid & 3) == 0) s->gmax[tid >> 2] = m;
    __syncthreads();

    // 30th-largest of 64 group maxes by rank counting (no sort).
    if (tid < 64) {
        float v = s->gmax[tid];
        int r = 0;
#pragma unroll 8
        for (int j = 0; j < 64; j++) {
            float o = s->gmax[j];
            r += (o > v) || (o == v && j < tid);
        }
        if (r == KTOP - 1) s->th = v;   // th <= 30th-largest element of the row
    }
    __syncthreads();
    const float th = s->th;

    // ---- Filter bootstrap chunk from registers (no re-read) ----
#pragma unroll
    for (int k = 0; k < 8; k++)
        filt4(w[k], (unsigned)((tid + (k << 8)) << 2), th, s);

    // ---- Stream the remaining elems once: full batches unguarded ----
    int base = BOOT4;
    for (; base + NTHREADS * 8 <= NF4; base += NTHREADS * 8) {
        float4 u[8];
#pragma unroll
        for (int k = 0; k < 8; k++) u[k] = __ldg(&row4[base + (k << 8) + tid]);
#pragma unroll
        for (int k = 0; k < 8; k++)
            filt4(u[k], (unsigned)((base + (k << 8) + tid) << 2), th, s);
    }
    // ---- guarded tail ----
    {
        const float qnan = __int_as_float(0x7fc00000);
        float4 u[8];
#pragma unroll
        for (int k = 0; k < 8; k++) {
            int j4 = base + (k << 8) + tid;
            u[k] = (j4 < NF4) ? __ldg(&row4[j4])
                              : make_float4(qnan, qnan, qnan, qnan);
        }
#pragma unroll
        for (int k = 0; k < 8; k++)
            filt4(u[k], (unsigned)((base + (k << 8) + tid) << 2), th, s);
    }
    __syncthreads();
    int cnt = s->cnt;

    // ---- Fallback (statistically never taken): exact 30x argmax ----
    if (cnt > CAP) {
        unsigned long long prev = 0xFFFFFFFFFFFFFFFFull;
        for (int r = 0; r < KTOP; r++) {
            unsigned long long best = 0ull;
            for (int j4 = tid; j4 < NF4; j4 += NTHREADS) {
                float4 v = __ldg(&row4[j4]);
                unsigned e = (unsigned)(j4 << 2);
                unsigned long long kk;
                kk = mkkey(v.x, e);     if (kk < prev && kk > best) best = kk;
                kk = mkkey(v.y, e + 1); if (kk < prev && kk > best) best = kk;
                kk = mkkey(v.z, e + 2); if (kk < prev && kk > best) best = kk;
                kk = mkkey(v.w, e + 3); if (kk < prev && kk > best) best = kk;
            }
#pragma unroll
            for (int o = 16; o > 0; o >>= 1) {
                unsigned long long ot = __shfl_xor_sync(0xFFFFFFFFu, best, o);
                if (ot > best) best = ot;
            }
            if ((tid & 31) == 0) s->wred[tid >> 5] = best;
            __syncthreads();
            if (tid == 0) {
                unsigned long long bb = s->wred[0];
                for (int i = 1; i < 8; i++) if (s->wred[i] > bb) bb = s->wred[i];
                s->buf[r] = bb;
            }
            __syncthreads();
            prev = s->buf[r];
        }
        cnt = KTOP;
    }

    // ---- Exact top-30 set by rank counting (keys unique; no sort) ----
    for (int i = tid; i < cnt; i += NTHREADS) {
        unsigned long long key = s->buf[i];
        int r = 0;
        for (int j = 0; j < cnt; j++) r += (s->buf[j] > key);
        if (r < KTOP) outIdx[r] = (int)(~(unsigned)key);
    }
    __syncthreads();
}

__global__ __launch_bounds__(NTHREADS)
void topk_loss_kernel(const float* __restrict__ logits,
                      const float* __restrict__ targets,
                      int B, float* __restrict__ out) {
    __shared__ SMem s;
    const int row = blockIdx.x;
    const int tid = threadIdx.x;
    const size_t off = (size_t)row * CCOLS;

    topk_select((const float4*)(targets + off), &s, s.tIdx);
    topk_select((const float4*)(logits + off),  &s, s.lIdx);

    // threads 0..29 live in warp 0 -> deterministic shfl reductions
    if (tid < 32) {
        float li = 0.0f;
        int   c  = 0;
        if (tid < KTOP) {
            int my = s.tIdx[tid];
#pragma unroll
            for (int i = 0; i < KTOP; i++) c += (my == s.lIdx[i]);
            float x = __ldg(&logits[off + (size_t)my]);   // L2-hot gather
            float p = 1.0f / (1.0f + expf(-x));
            li = -logf(p + 1e-7f);
        }
#pragma unroll
        for (int o = 16; o > 0; o >>= 1) {
            li += __shfl_xor_sync(0xFFFFFFFFu, li, o);
            c  += __shfl_xor_sync(0xFFFFFFFFu, c,  o);
        }
        if (tid == 0) {
            float lm = li * (1.0f / KTOP);
            float w  = 1.0f - (float)c * (1.0f / KTOP);
            g_rowloss[row] = lm * w;
        }
    }

    // ---- last CTA performs deterministic ordered mean ----
    if (tid == 0) {
        unsigned t;
        // release: all prior writes (g_rowloss[row]) visible before ticket.
        asm volatile("atom.add.release.gpu.u32 %0, [%1], 1;"
                     : "=r"(t) : "l"(&g_done) : "memory");
        s.isLast = (t == (unsigned)(gridDim.x - 1));
    }
    __syncthreads();
    if (s.isLast) {
        // acquire: see all CTAs' g_rowloss writes.
        if (tid == 0) {
            unsigned dummy;
            asm volatile("atom.exch.acquire.gpu.b32 %0, [%1], 0;"
                         : "=r"(dummy) : "l"(&g_done) : "memory");  // also resets
        }
        __syncthreads();
        float sum = 0.0f;
        for (int i = tid; i < B; i += NTHREADS) sum += g_rowloss[i];
#pragma unroll
        for (int o = 16; o > 0; o >>= 1)
            sum += __shfl_xor_sync(0xFFFFFFFFu, sum, o);
        __shared__ float red[8];
        if ((tid & 31) == 0) red[tid >> 5] = sum;
        __syncthreads();
        if (tid == 0) {
            float t2 = 0.0f;
#pragma unroll
            for (int i = 0; i < 8; i++) t2 += red[i];
            out[0] = t2 / (float)B;
        }
    }
}

extern "C" void kernel_launch(void* const* d_in, const int* in_sizes, int n_in,
                              void* d_out, int out_size) {
    const float* logits  = (const float*)d_in[0];
    const float* targets = (const float*)d_in[1];
    int B = in_sizes[0] / CCOLS;
    if (B > MAXB) B = MAXB;
    topk_loss_kernel<<<B, NTHREADS>>>(logits, targets, B, (float*)d_out);
}

// round 12
// speedup vs baseline: 1.0937x; 1.0937x over previous
#include <cuda_runtime.h>
#include <cstdint>

#define NTHREADS 256
#define KTOP 30
#define CCOLS 32000
#define NF4 8000          // float4 per row
#define BOOT4 2048        // float4 in bootstrap chunk (8192 floats)
#define CAP 1024
#define MAXB 4096

__device__ float g_rowloss[MAXB];
__device__ unsigned g_done = 0;

__device__ __forceinline__ unsigned ordu(float f) {
    unsigned u = __float_as_uint(f);
    return (u & 0x80000000u) ? ~u : (u | 0x80000000u);
}
// key: order-preserving float in high bits, ~index low => unique keys,
// equal values break ties toward smaller index (matches jax top_k).
__device__ __forceinline__ unsigned long long mkkey(float f, unsigned idx) {
    return (((unsigned long long)ordu(f)) << 32) | (unsigned long long)(~idx);
}

struct SMem {
    unsigned long long buf[CAP];
    unsigned long long wred[8];
    float gmax[64];
    int   tIdx[KTOP];
    int   lIdx[KTOP];
    float th;
    int   cnt;
    int   isLast;
};

// Exact top-30 index set of one row. On return (synced): outIdx[0..29] filled
// (rank order, but callers only treat it as a set).
__device__ void topk_select(const float4* __restrict__ row4, SMem* s, int* outIdx) {
    const int tid = threadIdx.x;
    if (tid == 0) s->cnt = 0;

    // ---- Bootstrap: load first 8192 elems into regs, derive safe threshold ----
    float4 w[8];
    float m = -3.402823466e38f;
#pragma unroll
    for (int k = 0; k < 8; k++) {
        w[k] = __ldg(&row4[tid + (k << 8)]);
        m = fmaxf(m, fmaxf(fmaxf(w[k].x, w[k].y), fmaxf(w[k].z, w[k].w)));
    }
    m = fmaxf(m, __shfl_xor_sync(0xFFFFFFFFu, m, 1));
    m = fmaxf(m, __shfl_xor_sync(0xFFFFFFFFu, m, 2));
    if ((tid & 3) == 0) s->gmax[tid >> 2] = m;
    __syncthreads();

    // 30th-largest of 64 group maxes by rank counting (no sort).
    if (tid < 64) {
        float v = s->gmax[tid];
        int r = 0;
#pragma unroll 8
        for (int j = 0; j < 64; j++) {
            float o = s->gmax[j];
            r += (o > v) || (o == v && j < tid);
        }
        if (r == KTOP - 1) s->th = v;   // th <= 30th-largest element of the row
    }
    __syncthreads();
    const float th = s->th;

    // ---- Filter bootstrap chunk from registers (no re-read) ----
#pragma unroll
    for (int k = 0; k < 8; k++) {
        unsigned e = (unsigned)((tid + (k << 8)) << 2);
        float4 v = w[k];
        if (v.x >= th) { int p = atomicAdd(&s->cnt, 1); if (p < CAP) s->buf[p] = mkkey(v.x, e); }
        if (v.y >= th) { int p = atomicAdd(&s->cnt, 1); if (p < CAP) s->buf[p] = mkkey(v.y, e + 1); }
        if (v.z >= th) { int p = atomicAdd(&s->cnt, 1); if (p < CAP) s->buf[p] = mkkey(v.z, e + 2); }
        if (v.w >= th) { int p = atomicAdd(&s->cnt, 1); if (p < CAP) s->buf[p] = mkkey(v.w, e + 3); }
    }

    // ---- Stream the remaining 23808 elems once ----
    const float qnan = __int_as_float(0x7fc00000);
    for (int base = BOOT4; base < NF4; base += NTHREADS * 8) {
        float4 u[8];
#pragma unroll
        for (int k = 0; k < 8; k++) {
            int j4 = base + (k << 8) + tid;
            u[k] = (j4 < NF4) ? __ldg(&row4[j4])
                              : make_float4(qnan, qnan, qnan, qnan);
        }
#pragma unroll
        for (int k = 0; k < 8; k++) {
            int j4 = base + (k << 8) + tid;
            unsigned e = (unsigned)(j4 << 2);
            float4 v = u[k];
            if (v.x >= th) { int p = atomicAdd(&s->cnt, 1); if (p < CAP) s->buf[p] = mkkey(v.x, e); }
            if (v.y >= th) { int p = atomicAdd(&s->cnt, 1); if (p < CAP) s->buf[p] = mkkey(v.y, e + 1); }
            if (v.z >= th) { int p = atomicAdd(&s->cnt, 1); if (p < CAP) s->buf[p] = mkkey(v.z, e + 2); }
            if (v.w >= th) { int p = atomicAdd(&s->cnt, 1); if (p < CAP) s->buf[p] = mkkey(v.w, e + 3); }
        }
    }
    __syncthreads();
    int cnt = s->cnt;

    // ---- Fallback (statistically never taken): exact 30x argmax ----
    if (cnt > CAP) {
        unsigned long long prev = 0xFFFFFFFFFFFFFFFFull;
        for (int r = 0; r < KTOP; r++) {
            unsigned long long best = 0ull;
            for (int j4 = tid; j4 < NF4; j4 += NTHREADS) {
                float4 v = __ldg(&row4[j4]);
                unsigned e = (unsigned)(j4 << 2);
                unsigned long long kk;
                kk = mkkey(v.x, e);     if (kk < prev && kk > best) best = kk;
                kk = mkkey(v.y, e + 1); if (kk < prev && kk > best) best = kk;
                kk = mkkey(v.z, e + 2); if (kk < prev && kk > best) best = kk;
                kk = mkkey(v.w, e + 3); if (kk < prev && kk > best) best = kk;
            }
#pragma unroll
            for (int o = 16; o > 0; o >>= 1) {
                unsigned long long ot = __shfl_xor_sync(0xFFFFFFFFu, best, o);
                if (ot > best) best = ot;
            }
            if ((tid & 31) == 0) s->wred[tid >> 5] = best;
            __syncthreads();
            if (tid == 0) {
                unsigned long long bb = s->wred[0];
                for (int i = 1; i < 8; i++) if (s->wred[i] > bb) bb = s->wred[i];
                s->buf[r] = bb;
            }
            __syncthreads();
            prev = s->buf[r];
        }
        cnt = KTOP;
    }

    // ---- Exact top-30 set by rank counting (keys unique; no sort) ----
    for (int i = tid; i < cnt; i += NTHREADS) {
        unsigned long long key = s->buf[i];
        int r = 0;
        for (int j = 0; j < cnt; j++) r += (s->buf[j] > key);
        if (r < KTOP) outIdx[r] = (int)(~(unsigned)key);
    }
    __syncthreads();
}

__global__ __launch_bounds__(NTHREADS, 6)
void topk_loss_kernel(const float* __restrict__ logits,
                      const float* __restrict__ targets,
                      int B, float* __restrict__ out) {
    __shared__ SMem s;
    const int row = blockIdx.x;
    const int tid = threadIdx.x;
    const size_t off = (size_t)row * CCOLS;

    topk_select((const float4*)(targets + off), &s, s.tIdx);
    topk_select((const float4*)(logits + off),  &s, s.lIdx);

    // threads 0..29 live in warp 0 -> deterministic shfl reductions
    if (tid < 32) {
        float li = 0.0f;
        int   c  = 0;
        if (tid < KTOP) {
            int my = s.tIdx[tid];
#pragma unroll
            for (int i = 0; i < KTOP; i++) c += (my == s.lIdx[i]);
            float x = __ldg(&logits[off + (size_t)my]);   // L2-hot gather
            float p = 1.0f / (1.0f + expf(-x));
            li = -logf(p + 1e-7f);
        }
#pragma unroll
        for (int o = 16; o > 0; o >>= 1) {
            li += __shfl_xor_sync(0xFFFFFFFFu, li, o);
            c  += __shfl_xor_sync(0xFFFFFFFFu, c,  o);
        }
        if (tid == 0) {
            float lm = li * (1.0f / KTOP);
            float w  = 1.0f - (float)c * (1.0f / KTOP);
            g_rowloss[row] = lm * w;
        }
    }

    // ---- last CTA performs deterministic ordered mean ----
    if (tid == 0) {
        unsigned t;
        // release: all prior writes (g_rowloss[row]) visible before ticket.
        asm volatile("atom.add.release.gpu.u32 %0, [%1], 1;"
                     : "=r"(t) : "l"(&g_done) : "memory");
        s.isLast = (t == (unsigned)(gridDim.x - 1));
    }
    __syncthreads();
    if (s.isLast) {
        // acquire: see all CTAs' g_rowloss writes.
        if (tid == 0) {
            unsigned dummy;
            asm volatile("atom.exch.acquire.gpu.b32 %0, [%1], 0;"
                         : "=r"(dummy) : "l"(&g_done) : "memory");  // also resets
        }
        __syncthreads();
        float sum = 0.0f;
        for (int i = tid; i < B; i += NTHREADS) sum += g_rowloss[i];
#pragma unroll
        for (int o = 16; o > 0; o >>= 1)
            sum += __shfl_xor_sync(0xFFFFFFFFu, sum, o);
        __shared__ float red[8];
        if ((tid & 31) == 0) red[tid >> 5] = sum;
        __syncthreads();
        if (tid == 0) {
            float t2 = 0.0f;
#pragma unroll
            for (int i = 0; i < 8; i++) t2 += red[i];
            out[0] = t2 / (float)B;
        }
    }
}

extern "C" void kernel_launch(void* const* d_in, const int* in_sizes, int n_in,
                              void* d_out, int out_size) {
    const float* logits  = (const float*)d_in[0];
    const float* targets = (const float*)d_in[1];
    int B = in_sizes[0] / CCOLS;
    if (B > MAXB) B = MAXB;
    topk_loss_kernel<<<B, NTHREADS>>>(logits, targets, B, (float*)d_out);
}